// round 6
// baseline (speedup 1.0000x reference)
#include <cuda_runtime.h>
#include <cuda_bf16.h>
#include <cstddef>

// EMA: out[b,t,c] = 0.1*x + 0.9*out[b,t-1,c], out[b,0,c]=x[b,0,c].
// (16, 4096, 512) fp32. Time-parallel truncated lookback (0.9^128 ~ 1.4e-6).
//
// R5 -> R6: float2 vectorization (LDG.64) for 2x bytes-in-flight per load
// slot, 64-thread blocks to keep 1024 warps / 512 blocks for spread, and
// __stcs streaming stores so the write-once output doesn't evict x from L2
// (lookback reads re-touch x).

namespace {
constexpr int B = 16;
constexpr int T = 4096;
constexpr int C = 512;
constexpr int C2 = C / 2;             // 256 float2 columns
constexpr int SEG_LEN = 512;
constexpr int NSEG = T / SEG_LEN;     // 8
constexpr int LOOKBACK = 128;         // 0.9^128 ~ 1.4e-6
constexpr int BLOCK_THREADS = 64;     // 64 float2 lanes = 128 channels
constexpr float ALPHA = 0.1f;
constexpr float BETA  = 0.9f;
}

__global__ __launch_bounds__(BLOCK_THREADS, 16)
void ema_lookback_v2_kernel(const float2* __restrict__ x, float2* __restrict__ out) {
    const int c2  = blockIdx.x * BLOCK_THREADS + threadIdx.x;  // float2 column
    const int seg = blockIdx.y;
    const int b   = blockIdx.z;

    const size_t base = (size_t)b * T * C2 + (size_t)c2;
    const float2* __restrict__ xp = x   + base;
    float2*       __restrict__ op = out + base;

    const int t0 = seg * SEG_LEN;
    float2 y;
    int tstart;

    if (seg == 0) {
        y = xp[0];
        __stcs(&op[0], y);
        tstart = 1;
    } else {
        // Warm-up from zero init over LOOKBACK steps.
        y.x = 0.0f; y.y = 0.0f;
        const int tl = t0 - LOOKBACK;
        #pragma unroll 16
        for (int k = 0; k < LOOKBACK; ++k) {
            const float2 xv = xp[(size_t)(tl + k) * C2];
            y.x = fmaf(BETA, y.x, ALPHA * xv.x);
            y.y = fmaf(BETA, y.y, ALPHA * xv.y);
        }
        tstart = t0;
    }

    const int tend = t0 + SEG_LEN;
    #pragma unroll 16
    for (int t = tstart; t < tend; ++t) {
        const float2 xv = xp[(size_t)t * C2];
        y.x = fmaf(BETA, y.x, ALPHA * xv.x);
        y.y = fmaf(BETA, y.y, ALPHA * xv.y);
        __stcs(&op[(size_t)t * C2], y);   // streaming: write-once, never read
    }
}

extern "C" void kernel_launch(void* const* d_in, const int* in_sizes, int n_in,
                              void* d_out, int out_size) {
    (void)in_sizes; (void)n_in; (void)out_size;
    const float2* x = (const float2*)d_in[0];
    float2* out = (float2*)d_out;

    dim3 grid(C2 / BLOCK_THREADS, NSEG, B);  // (4, 8, 16) = 512 blocks
    dim3 block(BLOCK_THREADS);               // 64 threads (2 warps)
    ema_lookback_v2_kernel<<<grid, block>>>(x, out);
}